// round 9
// baseline (speedup 1.0000x reference)
#include <cuda_runtime.h>
#include <cstdint>

// ChamferDistance on GB300 — Round 9: exact nearest-neighbor via z-bucket
// projection search (brute force is FFMA2-bank-bound at ~134us; this prunes
// ~15x of the math while remaining exact).
//
// Stage 1 (cd_bucket_kernel): per (set,batch), bucket the 8192 points by z
//   into 256 buckets (counting sort). Store float4(x,y,z,||p||^2) + orig idx.
// Stage 2 (cd_nn_kernel): each thread takes one SORTED query point (warp is
//   z-coherent), scans ref buckets outward from its z, terminating a
//   direction when (edge z-distance)^2 >= best d. Exact: d >= dz^2.

#define NB  256           // z-buckets per (set,batch)
#define ST  256           // sort kernel threads
#define QT  256           // query kernel threads
#define MAXP 8192
#define MAXB 8

__device__ float4 g_pts [2][MAXB * MAXP];   // bucketed points (x,y,z,sq)
__device__ int    g_idx [2][MAXB * MAXP];   // original index of each point
__device__ int    g_off [2][MAXB][NB + 1];  // bucket offsets
__device__ float  g_zmin[2][MAXB];
__device__ float  g_w   [2][MAXB];
__device__ float  g_invw[2][MAXB];

__global__ __launch_bounds__(ST)
void cd_bucket_kernel(const float* __restrict__ xyz1,
                      const float* __restrict__ xyz2,
                      int Npts)
{
    const int set = blockIdx.y;
    const int b   = blockIdx.x;
    const float* __restrict__ src =
        ((set == 0) ? xyz1 : xyz2) + (size_t)b * Npts * 3;
    const int tid = threadIdx.x;

    __shared__ float s_red[ST];
    __shared__ int   s_hist[NB];
    __shared__ int   s_off[NB + 1];
    __shared__ int   s_cur[NB];
    __shared__ float s_zmin, s_invw;

    // ---- pass 1: z min/max ----
    float zmn = 3.402823466e+38f, zmx = -3.402823466e+38f;
    for (int j = tid; j < Npts; j += ST) {
        float z = src[j * 3 + 2];
        zmn = fminf(zmn, z);
        zmx = fmaxf(zmx, z);
    }
    s_red[tid] = zmn; __syncthreads();
    for (int s = ST / 2; s > 0; s >>= 1) {
        if (tid < s) s_red[tid] = fminf(s_red[tid], s_red[tid + s]);
        __syncthreads();
    }
    float zlo = s_red[0]; __syncthreads();
    s_red[tid] = zmx; __syncthreads();
    for (int s = ST / 2; s > 0; s >>= 1) {
        if (tid < s) s_red[tid] = fmaxf(s_red[tid], s_red[tid + s]);
        __syncthreads();
    }
    if (tid == 0) {
        float zhi = s_red[0];
        float w = (zhi - zlo) / NB;
        if (!(w > 0.f)) w = 1e-30f;
        s_zmin = zlo;
        s_invw = 1.0f / w;
        g_zmin[set][b] = zlo;
        g_w[set][b]    = w;
        g_invw[set][b] = 1.0f / w;
    }
    if (tid < NB) s_hist[tid] = 0;
    __syncthreads();

    // ---- pass 2: histogram ----
    for (int j = tid; j < Npts; j += ST) {
        float z = src[j * 3 + 2];
        int bb = (int)((z - s_zmin) * s_invw);
        bb = min(NB - 1, max(0, bb));
        atomicAdd(&s_hist[bb], 1);
    }
    __syncthreads();
    if (tid == 0) {
        int acc = 0;
        for (int i = 0; i < NB; i++) { s_off[i] = acc; acc += s_hist[i]; }
        s_off[NB] = acc;
    }
    __syncthreads();
    if (tid < NB) s_cur[tid] = s_off[tid];
    g_off[set][b][tid] = s_off[tid];
    if (tid == 0) g_off[set][b][NB] = s_off[NB];
    __syncthreads();

    // ---- pass 3: scatter ----
    float4* __restrict__ dst = &g_pts[set][(size_t)b * Npts];
    int*    __restrict__ di  = &g_idx[set][(size_t)b * Npts];
    for (int j = tid; j < Npts; j += ST) {
        float x = src[j * 3 + 0];
        float y = src[j * 3 + 1];
        float z = src[j * 3 + 2];
        int bb = (int)((z - s_zmin) * s_invw);
        bb = min(NB - 1, max(0, bb));
        int pos = atomicAdd(&s_cur[bb], 1);
        dst[pos] = make_float4(x, y, z, fmaf(x, x, fmaf(y, y, z * z)));
        di[pos]  = j;
    }
}

__global__ __launch_bounds__(QT)
void cd_nn_kernel(float* __restrict__ out, int Npts, int B)
{
    const int dir = blockIdx.z;           // 0: q=set0 r=set1 ; 1: swapped
    const int b   = blockIdx.y;
    const int i   = blockIdx.x * QT + threadIdx.x;   // sorted query index
    if (i >= Npts) return;

    const int qset = dir;
    const int rset = 1 - dir;

    const float4 qp  = g_pts[qset][(size_t)b * Npts + i];
    const int   oidx = g_idx[qset][(size_t)b * Npts + i];
    const float qsq  = qp.w;
    const float zq   = qp.z;
    const float qx2 = -2.0f * qp.x;
    const float qy2 = -2.0f * qp.y;
    const float qz2 = -2.0f * qp.z;

    const float zmin = g_zmin[rset][b];
    const float invw = g_invw[rset][b];
    const float w    = g_w[rset][b];
    const float4* __restrict__ R  = &g_pts[rset][(size_t)b * Npts];
    const int*    __restrict__ off = g_off[rset][b];

    float me = 3.402823466e+38f;   // min_j ( sq_j - 2<q,r_j> ), shifted by -qsq

    // Scan one bucket: exact e_j for every point in it.
    auto scan = [&](int bb) {
        int j  = off[bb];
        int je = off[bb + 1];
        for (; j < je; ++j) {
            float4 r = R[j];
            float e = fmaf(qx2, r.x, fmaf(qy2, r.y, fmaf(qz2, r.z, r.w)));
            me = fminf(me, e);
        }
    };

    int bq = (int)((zq - zmin) * invw);
    bq = min(NB - 1, max(0, bq));
    scan(bq);

    int lo = bq - 1, hi = bq + 1;
    for (;;) {
        float lim = me + qsq;      // current best true distance
        float tlo = (lo >= 0) ? fmaxf(zq - (zmin + (float)(lo + 1) * w), 0.f)
                              : 3.402823466e+38f;
        float thi = (hi < NB) ? fmaxf((zmin + (float)hi * w) - zq, 0.f)
                              : 3.402823466e+38f;
        bool okLo = (lo >= 0) && (tlo * tlo < lim);
        bool okHi = (hi < NB) && (thi * thi < lim);
        if (!okLo && !okHi) break;
        if (okLo && (!okHi || tlo <= thi)) { scan(lo); --lo; }
        else                               { scan(hi); ++hi; }
    }

    float d = fmaxf(me + qsq, 0.0f);
    float* o = out + ((dir == 0) ? 0 : (size_t)B * Npts);
    o[(size_t)b * Npts + oidx] = d;
}

extern "C" void kernel_launch(void* const* d_in, const int* in_sizes, int n_in,
                              void* d_out, int out_size)
{
    const float* xyz1 = (const float*)d_in[0];
    const float* xyz2 = (const float*)d_in[1];
    float* out = (float*)d_out;

    const int B = 8;
    const int N = (in_sizes[0] / 3) / B;   // 8192 (== M)

    // Stage 1: bucket both sets, all batches. 16 CTAs.
    {
        dim3 grid(B, 2);
        cd_bucket_kernel<<<grid, ST>>>(xyz1, xyz2, N);
    }

    // Stage 2: exact NN for every query in both directions.
    {
        dim3 grid((N + QT - 1) / QT, B, 2);   // 32 x 8 x 2 = 512 CTAs
        cd_nn_kernel<<<grid, QT>>>(out, N, B);
    }
}

// round 10
// speedup vs baseline: 2.6710x; 2.6710x over previous
#include <cuda_runtime.h>
#include <cstdint>

// ChamferDistance on GB300 — Round 10: exact NN via z-sorted block-cooperative
// pruned scan. Stage 1: bucket both sets by z (counting sort, 256 buckets).
// Stage 2: each CTA owns 512 contiguous sorted queries, streams bucket-aligned
// ref tiles through SoA smem (R5 inner loop: f32x2 FFMA, broadcast LDS),
// expanding outward in z and terminating per direction when
// max(zq_edge_margin,0)^2 >= block-max current best. Exact, divergence-free.

#define NB   256          // z-buckets per (set,batch)
#define ST   256          // sort kernel threads
#define QT   256          // NN kernel threads
#define QP   2            // queries per thread -> 512 queries per CTA
#define TILE 256          // ref points staged per smem tile
#define BSTEP 8           // buckets appended per expansion step (~256 refs)
#define MAXP 8192
#define MAXB 8

__device__ float4 g_pts [2][MAXB * MAXP];   // z-bucketed points (x,y,z,||p||^2)
__device__ int    g_idx [2][MAXB * MAXP];   // original index of each point
__device__ int    g_off [2][MAXB][NB + 1];  // bucket offsets
__device__ float  g_zmin[2][MAXB];
__device__ float  g_w   [2][MAXB];
__device__ float  g_invw[2][MAXB];

// ---------------- Stage 1: z counting sort (verbatim from R9, validated) ----
__global__ __launch_bounds__(ST)
void cd_bucket_kernel(const float* __restrict__ xyz1,
                      const float* __restrict__ xyz2,
                      int Npts)
{
    const int set = blockIdx.y;
    const int b   = blockIdx.x;
    const float* __restrict__ src =
        ((set == 0) ? xyz1 : xyz2) + (size_t)b * Npts * 3;
    const int tid = threadIdx.x;

    __shared__ float s_red[ST];
    __shared__ int   s_hist[NB];
    __shared__ int   s_off[NB + 1];
    __shared__ int   s_cur[NB];
    __shared__ float s_zmin, s_invw;

    float zmn = 3.402823466e+38f, zmx = -3.402823466e+38f;
    for (int j = tid; j < Npts; j += ST) {
        float z = src[j * 3 + 2];
        zmn = fminf(zmn, z);
        zmx = fmaxf(zmx, z);
    }
    s_red[tid] = zmn; __syncthreads();
    for (int s = ST / 2; s > 0; s >>= 1) {
        if (tid < s) s_red[tid] = fminf(s_red[tid], s_red[tid + s]);
        __syncthreads();
    }
    float zlo = s_red[0]; __syncthreads();
    s_red[tid] = zmx; __syncthreads();
    for (int s = ST / 2; s > 0; s >>= 1) {
        if (tid < s) s_red[tid] = fmaxf(s_red[tid], s_red[tid + s]);
        __syncthreads();
    }
    if (tid == 0) {
        float zhi = s_red[0];
        float w = (zhi - zlo) / NB;
        if (!(w > 0.f)) w = 1e-30f;
        s_zmin = zlo;
        s_invw = 1.0f / w;
        g_zmin[set][b] = zlo;
        g_w[set][b]    = w;
        g_invw[set][b] = 1.0f / w;
    }
    if (tid < NB) s_hist[tid] = 0;
    __syncthreads();

    for (int j = tid; j < Npts; j += ST) {
        float z = src[j * 3 + 2];
        int bb = min(NB - 1, max(0, (int)((z - s_zmin) * s_invw)));
        atomicAdd(&s_hist[bb], 1);
    }
    __syncthreads();
    if (tid == 0) {
        int acc = 0;
        for (int i = 0; i < NB; i++) { s_off[i] = acc; acc += s_hist[i]; }
        s_off[NB] = acc;
    }
    __syncthreads();
    if (tid < NB) s_cur[tid] = s_off[tid];
    g_off[set][b][tid] = s_off[tid];
    if (tid == 0) g_off[set][b][NB] = s_off[NB];
    __syncthreads();

    float4* __restrict__ dst = &g_pts[set][(size_t)b * Npts];
    int*    __restrict__ di  = &g_idx[set][(size_t)b * Npts];
    for (int j = tid; j < Npts; j += ST) {
        float x = src[j * 3 + 0];
        float y = src[j * 3 + 1];
        float z = src[j * 3 + 2];
        int bb = min(NB - 1, max(0, (int)((z - s_zmin) * s_invw)));
        int pos = atomicAdd(&s_cur[bb], 1);
        dst[pos] = make_float4(x, y, z, fmaf(x, x, fmaf(y, y, z * z)));
        di[pos]  = j;
    }
}

// ---------------- helpers ----------------
__device__ __forceinline__ uint64_t cd_dup2(float v) {
    uint64_t r;
    asm("mov.b64 %0, {%1, %1};" : "=l"(r) : "r"(__float_as_uint(v)));
    return r;
}

__device__ __forceinline__ void cd_dot2(uint64_t qx, uint64_t qy, uint64_t qz,
                                        uint64_t px, uint64_t py, uint64_t pz,
                                        uint64_t s,
                                        float& dlo, float& dhi) {
    uint32_t lo, hi;
    asm("{\n\t"
        ".reg .b64 t;\n\t"
        "fma.rn.f32x2 t, %2, %3, %4;\n\t"
        "fma.rn.f32x2 t, %5, %6, t;\n\t"
        "fma.rn.f32x2 t, %7, %8, t;\n\t"
        "mov.b64 {%0, %1}, t;\n\t"
        "}"
        : "=r"(lo), "=r"(hi)
        : "l"(qz), "l"(pz), "l"(s),
          "l"(qy), "l"(py),
          "l"(qx), "l"(px));
    dlo = __uint_as_float(lo);
    dhi = __uint_as_float(hi);
}

__device__ __forceinline__ float blk_max(float v, float* s_red, int tid) {
    #pragma unroll
    for (int o = 16; o; o >>= 1) v = fmaxf(v, __shfl_xor_sync(0xFFFFFFFFu, v, o));
    if ((tid & 31) == 0) s_red[tid >> 5] = v;
    __syncthreads();
    if (tid < 8) {
        float w = s_red[tid];
        #pragma unroll
        for (int o = 4; o; o >>= 1) w = fmaxf(w, __shfl_xor_sync(0xFFu, w, o));
        if (tid == 0) s_red[0] = w;
    }
    __syncthreads();
    float r = s_red[0];
    __syncthreads();
    return r;
}

__device__ __forceinline__ float blk_min(float v, float* s_red, int tid) {
    #pragma unroll
    for (int o = 16; o; o >>= 1) v = fminf(v, __shfl_xor_sync(0xFFFFFFFFu, v, o));
    if ((tid & 31) == 0) s_red[tid >> 5] = v;
    __syncthreads();
    if (tid < 8) {
        float w = s_red[tid];
        #pragma unroll
        for (int o = 4; o; o >>= 1) w = fminf(w, __shfl_xor_sync(0xFFu, w, o));
        if (tid == 0) s_red[0] = w;
    }
    __syncthreads();
    float r = s_red[0];
    __syncthreads();
    return r;
}

// ---------------- Stage 2: block-cooperative pruned NN ----------------
__global__ __launch_bounds__(QT, 3)
void cd_nn_kernel(float* __restrict__ out, int Npts, int B)
{
    const int dir  = blockIdx.z;           // 0: q=set0 r=set1 ; 1: swapped
    const int b    = blockIdx.y;
    const int qset = dir, rset = 1 - dir;
    const int tid  = threadIdx.x;
    const int q0   = blockIdx.x * (QT * QP);

    const float4* __restrict__ Q  = &g_pts[qset][(size_t)b * Npts];
    const int*    __restrict__ QI = &g_idx[qset][(size_t)b * Npts];
    const float4* __restrict__ R  = &g_pts[rset][(size_t)b * Npts];
    const int*    __restrict__ off = g_off[rset][b];
    const float zminR = g_zmin[rset][b];
    const float wR    = g_w[rset][b];
    const float invwR = g_invw[rset][b];

    __shared__ __align__(16) float sx[TILE];
    __shared__ __align__(16) float sy[TILE];
    __shared__ __align__(16) float sz[TILE];
    __shared__ __align__(16) float ss[TILE];
    __shared__ float s_red[8];

    // Load queries (sorted, contiguous -> coalesced float4)
    uint64_t qxd[QP], qyd[QP], qzd[QP];
    float qsq[QP], zq[QP], me[QP];
    int qi[QP];
    #pragma unroll
    for (int p = 0; p < QP; p++) {
        int ii = q0 + p * QT + tid;
        qi[p] = ii;
        float4 qp = Q[ii];
        qxd[p] = cd_dup2(-2.0f * qp.x);
        qyd[p] = cd_dup2(-2.0f * qp.y);
        qzd[p] = cd_dup2(-2.0f * qp.z);
        qsq[p] = qp.w;
        zq[p]  = qp.z;
        me[p]  = 3.402823466e+38f;
    }

    float zqmin = blk_min(fminf(zq[0], zq[1]), s_red, tid);
    float zqmax = blk_max(fmaxf(zq[0], zq[1]), s_red, tid);

    // Scan refs in index range [j0, j1) through smem tiles (R5 inner loop).
    auto scan_range = [&](int j0, int j1) {
        for (int base = j0; base < j1; base += TILE) {
            __syncthreads();
            {
                int j = base + tid;
                float x = 0.f, y = 0.f, z = 0.f, s = 3.402823466e+38f;
                if (j < j1) { float4 r = R[j]; x = r.x; y = r.y; z = r.z; s = r.w; }
                sx[tid] = x; sy[tid] = y; sz[tid] = z; ss[tid] = s;
            }
            __syncthreads();
            const uint64_t* __restrict__ px2 = (const uint64_t*)sx;
            const uint64_t* __restrict__ py2 = (const uint64_t*)sy;
            const uint64_t* __restrict__ pz2 = (const uint64_t*)sz;
            const uint64_t* __restrict__ ps2 = (const uint64_t*)ss;
            #pragma unroll 4
            for (int jj = 0; jj < TILE / 2; jj++) {
                uint64_t px = px2[jj], py = py2[jj];
                uint64_t pz = pz2[jj], ps = ps2[jj];
                #pragma unroll
                for (int p = 0; p < QP; p++) {
                    float dlo, dhi;
                    cd_dot2(qxd[p], qyd[p], qzd[p], px, py, pz, ps, dlo, dhi);
                    me[p] = fminf(me[p], fminf(dlo, dhi));
                }
            }
        }
        __syncthreads();
    };

    // Initial scanned bucket range: buckets covering [zqmin, zqmax]
    int blo = min(NB - 1, max(0, (int)((zqmin - zminR) * invwR)));
    int bhi = min(NB, min(NB - 1, max(0, (int)((zqmax - zminR) * invwR))) + 1);
    scan_range(off[blo], off[bhi]);

    // Expand outward with block-uniform termination.
    for (;;) {
        float dmax = blk_max(fmaxf(me[0] + qsq[0], me[1] + qsq[1]), s_red, tid);
        float mlo = fmaxf(zqmin - (zminR + (float)blo * wR), 0.0f);
        float mhi = fmaxf((zminR + (float)bhi * wR) - zqmax, 0.0f);
        bool okLo = (blo > 0)  && (mlo * mlo < dmax);
        bool okHi = (bhi < NB) && (mhi * mhi < dmax);
        if (!okLo && !okHi) break;
        if (okLo && (!okHi || mlo <= mhi)) {
            int nlo = max(blo - BSTEP, 0);
            scan_range(off[nlo], off[blo]);
            blo = nlo;
        } else {
            int nhi = min(bhi + BSTEP, NB);
            scan_range(off[bhi], off[nhi]);
            bhi = nhi;
        }
    }

    float* __restrict__ o = out + ((dir == 0) ? 0 : (size_t)B * Npts)
                          + (size_t)b * Npts;
    #pragma unroll
    for (int p = 0; p < QP; p++) {
        float d = fmaxf(me[p] + qsq[p], 0.0f);
        o[QI[qi[p]]] = d;
    }
}

extern "C" void kernel_launch(void* const* d_in, const int* in_sizes, int n_in,
                              void* d_out, int out_size)
{
    const float* xyz1 = (const float*)d_in[0];
    const float* xyz2 = (const float*)d_in[1];
    float* out = (float*)d_out;

    const int B = 8;
    const int N = (in_sizes[0] / 3) / B;   // 8192 (== M)

    {
        dim3 grid(B, 2);
        cd_bucket_kernel<<<grid, ST>>>(xyz1, xyz2, N);
    }
    {
        int qblocks = N / (QT * QP);              // 16
        dim3 grid(qblocks, B, 2);                 // 16 x 8 x 2 = 256 CTAs
        cd_nn_kernel<<<grid, QT>>>(out, N, B);
    }
}

// round 11
// speedup vs baseline: 2.9058x; 1.0879x over previous
#include <cuda_runtime.h>
#include <cstdint>

// ChamferDistance on GB300 — Round 11: exact NN, z-sorted block-cooperative
// pruned scan with per-query union bounds.
// Stage 1: counting-sort both sets by z into 256 buckets (float4 + orig idx).
// Stage 2: CTA = 256 contiguous sorted queries (128 thr x 2). Streams ref
// tiles through SoA smem (R5 inner loop), expanding in z until
//   high side: bucket_edge >= max_q(zq + sqrt(dq))
//   low  side: bucket_edge <= min_q(zq - sqrt(dq))
// Exact and divergence-free; each output written exactly once.

#define NB   256
#define ST   256          // sort threads
#define QT   128          // NN threads
#define QP   2            // queries per thread -> 256 per CTA
#define TILE 256
#define BSTEP 4
#define MAXP 8192
#define MAXB 8

__device__ float4 g_pts [2][MAXB * MAXP];
__device__ int    g_idx [2][MAXB * MAXP];
__device__ int    g_off [2][MAXB][NB + 1];
__device__ float  g_zmin[2][MAXB];
__device__ float  g_w   [2][MAXB];
__device__ float  g_invw[2][MAXB];

// ---------------- Stage 1: z counting sort ----------------
__global__ __launch_bounds__(ST)
void cd_bucket_kernel(const float* __restrict__ xyz1,
                      const float* __restrict__ xyz2,
                      int Npts)
{
    const int set = blockIdx.y;
    const int b   = blockIdx.x;
    const float* __restrict__ src =
        ((set == 0) ? xyz1 : xyz2) + (size_t)b * Npts * 3;
    const int tid = threadIdx.x;

    __shared__ float s_red[ST];
    __shared__ int   s_hist[NB];
    __shared__ int   s_off[NB + 1];
    __shared__ int   s_cur[NB];
    __shared__ float s_zmin, s_invw;

    float zmn = 3.402823466e+38f, zmx = -3.402823466e+38f;
    for (int j = tid; j < Npts; j += ST) {
        float z = src[j * 3 + 2];
        zmn = fminf(zmn, z);
        zmx = fmaxf(zmx, z);
    }
    s_red[tid] = zmn; __syncthreads();
    for (int s = ST / 2; s > 0; s >>= 1) {
        if (tid < s) s_red[tid] = fminf(s_red[tid], s_red[tid + s]);
        __syncthreads();
    }
    float zlo = s_red[0]; __syncthreads();
    s_red[tid] = zmx; __syncthreads();
    for (int s = ST / 2; s > 0; s >>= 1) {
        if (tid < s) s_red[tid] = fmaxf(s_red[tid], s_red[tid + s]);
        __syncthreads();
    }
    if (tid == 0) {
        float zhi = s_red[0];
        float w = (zhi - zlo) / NB;
        if (!(w > 0.f)) w = 1e-30f;
        s_zmin = zlo;
        s_invw = 1.0f / w;
        g_zmin[set][b] = zlo;
        g_w[set][b]    = w;
        g_invw[set][b] = 1.0f / w;
    }
    if (tid < NB) s_hist[tid] = 0;
    __syncthreads();

    for (int j = tid; j < Npts; j += ST) {
        float z = src[j * 3 + 2];
        int bb = min(NB - 1, max(0, (int)((z - s_zmin) * s_invw)));
        atomicAdd(&s_hist[bb], 1);
    }
    __syncthreads();
    if (tid == 0) {
        int acc = 0;
        for (int i = 0; i < NB; i++) { s_off[i] = acc; acc += s_hist[i]; }
        s_off[NB] = acc;
    }
    __syncthreads();
    if (tid < NB) s_cur[tid] = s_off[tid];
    g_off[set][b][tid] = s_off[tid];
    if (tid == 0) g_off[set][b][NB] = s_off[NB];
    __syncthreads();

    float4* __restrict__ dst = &g_pts[set][(size_t)b * Npts];
    int*    __restrict__ di  = &g_idx[set][(size_t)b * Npts];
    for (int j = tid; j < Npts; j += ST) {
        float x = src[j * 3 + 0];
        float y = src[j * 3 + 1];
        float z = src[j * 3 + 2];
        int bb = min(NB - 1, max(0, (int)((z - s_zmin) * s_invw)));
        int pos = atomicAdd(&s_cur[bb], 1);
        dst[pos] = make_float4(x, y, z, fmaf(x, x, fmaf(y, y, z * z)));
        di[pos]  = j;
    }
}

// ---------------- helpers ----------------
__device__ __forceinline__ uint64_t cd_dup2(float v) {
    uint64_t r;
    asm("mov.b64 %0, {%1, %1};" : "=l"(r) : "r"(__float_as_uint(v)));
    return r;
}

__device__ __forceinline__ void cd_dot2(uint64_t qx, uint64_t qy, uint64_t qz,
                                        uint64_t px, uint64_t py, uint64_t pz,
                                        uint64_t s,
                                        float& dlo, float& dhi) {
    uint32_t lo, hi;
    asm("{\n\t"
        ".reg .b64 t;\n\t"
        "fma.rn.f32x2 t, %2, %3, %4;\n\t"
        "fma.rn.f32x2 t, %5, %6, t;\n\t"
        "fma.rn.f32x2 t, %7, %8, t;\n\t"
        "mov.b64 {%0, %1}, t;\n\t"
        "}"
        : "=r"(lo), "=r"(hi)
        : "l"(qz), "l"(pz), "l"(s),
          "l"(qy), "l"(py),
          "l"(qx), "l"(px));
    dlo = __uint_as_float(lo);
    dhi = __uint_as_float(hi);
}

// Block reductions for QT=128 (4 warps). s_red must hold >= 4 floats.
__device__ __forceinline__ float blk_max(float v, volatile float* s_red, int tid) {
    #pragma unroll
    for (int o = 16; o; o >>= 1) v = fmaxf(v, __shfl_xor_sync(0xFFFFFFFFu, v, o));
    if ((tid & 31) == 0) s_red[tid >> 5] = v;
    __syncthreads();
    float r = fmaxf(fmaxf(s_red[0], s_red[1]), fmaxf(s_red[2], s_red[3]));
    __syncthreads();
    return r;
}
__device__ __forceinline__ float blk_min(float v, volatile float* s_red, int tid) {
    #pragma unroll
    for (int o = 16; o; o >>= 1) v = fminf(v, __shfl_xor_sync(0xFFFFFFFFu, v, o));
    if ((tid & 31) == 0) s_red[tid >> 5] = v;
    __syncthreads();
    float r = fminf(fminf(s_red[0], s_red[1]), fminf(s_red[2], s_red[3]));
    __syncthreads();
    return r;
}

// ---------------- Stage 2: block-cooperative pruned NN ----------------
__global__ __launch_bounds__(QT, 6)
void cd_nn_kernel(float* __restrict__ out, int Npts, int B)
{
    const int dir  = blockIdx.z;
    const int b    = blockIdx.y;
    const int qset = dir, rset = 1 - dir;
    const int tid  = threadIdx.x;
    const int q0   = blockIdx.x * (QT * QP);

    const float4* __restrict__ Q   = &g_pts[qset][(size_t)b * Npts];
    const int*    __restrict__ QI  = &g_idx[qset][(size_t)b * Npts];
    const float4* __restrict__ R   = &g_pts[rset][(size_t)b * Npts];
    const int*    __restrict__ off = g_off[rset][b];
    const float zminR = g_zmin[rset][b];
    const float wR    = g_w[rset][b];
    const float invwR = g_invw[rset][b];

    __shared__ __align__(16) float sx[TILE];
    __shared__ __align__(16) float sy[TILE];
    __shared__ __align__(16) float sz[TILE];
    __shared__ __align__(16) float ss[TILE];
    __shared__ float s_red[4];
    __shared__ float s_red2[4];

    uint64_t qxd[QP], qyd[QP], qzd[QP];
    float qsq[QP], zq[QP], me[QP];
    int qi[QP];
    #pragma unroll
    for (int p = 0; p < QP; p++) {
        int ii = q0 + p * QT + tid;
        qi[p] = ii;
        float4 qp = Q[ii];
        qxd[p] = cd_dup2(-2.0f * qp.x);
        qyd[p] = cd_dup2(-2.0f * qp.y);
        qzd[p] = cd_dup2(-2.0f * qp.z);
        qsq[p] = qp.w;
        zq[p]  = qp.z;
        me[p]  = 3.402823466e+38f;
    }

    float zqmin = blk_min(fminf(zq[0], zq[1]), s_red, tid);
    float zqmax = blk_max(fmaxf(zq[0], zq[1]), s_red, tid);

    auto scan_range = [&](int j0, int j1) {
        for (int base = j0; base < j1; base += TILE) {
            __syncthreads();
            for (int t = tid; t < TILE; t += QT) {
                int j = base + t;
                float x = 0.f, y = 0.f, z = 0.f, s = 3.402823466e+38f;
                if (j < j1) { float4 r = R[j]; x = r.x; y = r.y; z = r.z; s = r.w; }
                sx[t] = x; sy[t] = y; sz[t] = z; ss[t] = s;
            }
            __syncthreads();
            const uint64_t* __restrict__ px2 = (const uint64_t*)sx;
            const uint64_t* __restrict__ py2 = (const uint64_t*)sy;
            const uint64_t* __restrict__ pz2 = (const uint64_t*)sz;
            const uint64_t* __restrict__ ps2 = (const uint64_t*)ss;
            #pragma unroll 4
            for (int jj = 0; jj < TILE / 2; jj++) {
                uint64_t px = px2[jj], py = py2[jj];
                uint64_t pz = pz2[jj], ps = ps2[jj];
                #pragma unroll
                for (int p = 0; p < QP; p++) {
                    float dlo, dhi;
                    cd_dot2(qxd[p], qyd[p], qzd[p], px, py, pz, ps, dlo, dhi);
                    me[p] = fminf(me[p], fminf(dlo, dhi));
                }
            }
        }
        __syncthreads();
    };

    // Initial window: buckets covering the query z-span.
    int blo = min(NB - 1, max(0, (int)((zqmin - zminR) * invwR)));
    int bhi = min(NB, min(NB - 1, max(0, (int)((zqmax - zminR) * invwR))) + 1);
    scan_range(off[blo], off[bhi]);

    // Expansion with per-query union bounds:
    //   hi_need = max_q(zq + sqrt(dq)),  lo_need = min_q(zq - sqrt(dq)).
    for (;;) {
        float r0 = sqrtf(fmaxf(me[0] + qsq[0], 0.0f));
        float r1 = sqrtf(fmaxf(me[1] + qsq[1], 0.0f));
        float hi_need = blk_max(fmaxf(zq[0] + r0, zq[1] + r1), s_red,  tid);
        float lo_need = blk_min(fminf(zq[0] - r0, zq[1] - r1), s_red2, tid);

        bool okLo = (blo > 0)  && (zminR + (float)blo * wR > lo_need);
        bool okHi = (bhi < NB) && (zminR + (float)bhi * wR < hi_need);
        if (!okLo && !okHi) break;
        if (okLo) {
            int nlo = max(blo - BSTEP, 0);
            scan_range(off[nlo], off[blo]);
            blo = nlo;
        }
        if (okHi) {
            int nhi = min(bhi + BSTEP, NB);
            scan_range(off[bhi], off[nhi]);
            bhi = nhi;
        }
    }

    float* __restrict__ o = out + ((dir == 0) ? 0 : (size_t)B * Npts)
                          + (size_t)b * Npts;
    #pragma unroll
    for (int p = 0; p < QP; p++) {
        float d = fmaxf(me[p] + qsq[p], 0.0f);
        o[QI[qi[p]]] = d;
    }
}

extern "C" void kernel_launch(void* const* d_in, const int* in_sizes, int n_in,
                              void* d_out, int out_size)
{
    const float* xyz1 = (const float*)d_in[0];
    const float* xyz2 = (const float*)d_in[1];
    float* out = (float*)d_out;

    const int B = 8;
    const int N = (in_sizes[0] / 3) / B;   // 8192 (== M)

    {
        dim3 grid(B, 2);
        cd_bucket_kernel<<<grid, ST>>>(xyz1, xyz2, N);
    }
    {
        int qblocks = N / (QT * QP);              // 32
        dim3 grid(qblocks, B, 2);                 // 32 x 8 x 2 = 512 CTAs
        cd_nn_kernel<<<grid, QT>>>(out, N, B);
    }
}